// round 11
// baseline (speedup 1.0000x reference)
#include <cuda_runtime.h>
#include <cuda_fp16.h>
#include <cstdint>

// ---------------------------------------------------------------------------
// Seq2SeqForecast: 2-layer GRU encoder (B=512, T=336, H=512) + 48-step GRU
// decoder with scalar head.
//
// R10: persistent encoder kernel.
//  * 128 blocks, 1 CTA/SM (all co-resident), time loop inside the kernel with
//    a global-atomic grid barrier -> no per-step launches, no per-launch L1
//    flush, and weights live in SMEM for the entire encoder.
//  * Each block owns hidden-col tile of 16 (x3 gates) for Whh0/Whh1/Wih1:
//    3 x 48 rows x 520-half padded rows = 150KB SMEM, loaded once.
//  * Per iteration every block computes a layer0 M=128 tile then a layer1
//    M=128 tile (1-step lag keeps them independent); h fp16 A-tiles streamed
//    via cp.async.cg (L2-coherent) with a double buffer.
// Decoder unchanged from R9 (separate launches).
// ---------------------------------------------------------------------------

#define HDIM   512
#define BATCH  512
#define TSTEPS 336
#define HORIZON 48
#define G3H    (3 * HDIM)          // 1536

#define NBLK    128
#define WROWSTR 520                 // halves per weight row (pad: LDSM conflict-free)
#define WSLAB   (48 * WROWSTR)      // one matrix slab (3 gates x 16 cols)
#define WTOT    (3 * WSLAB)         // Whh0, Whh1, Wih1
#define ASTR    (128 * 40)          // A chunk buffer: 128 rows x 40 halves
#define PSMEM   ((WTOT + 4 * ASTR) * 2)   // 190720 bytes

// fp16 weight copies
__device__ __half g_Whh0[G3H * HDIM];
__device__ __half g_Wih1[G3H * HDIM];
__device__ __half g_Whh1[G3H * HDIM];
__device__ __half g_cWhh[G3H * HDIM];

// hidden-state ping-pong buffers (fp32 master + fp16 shadow for MMA)
__device__ float  g_h0_f32[2][BATCH * HDIM];
__device__ __half g_h0_f16[2][BATCH * HDIM];
__device__ float  g_h1_f32[2][BATCH * HDIM];
__device__ __half g_h1_f16[2][BATCH * HDIM];
__device__ float  g_hd_f32[2][BATCH * HDIM];
__device__ __half g_hd_f16[2][BATCH * HDIM];
__device__ float  g_lastv[BATCH];

// grid barrier state
__device__ unsigned g_bar_cnt;
__device__ unsigned g_bar_gen;

// ---------------------------------------------------------------------------
// helpers
// ---------------------------------------------------------------------------
__device__ __forceinline__ void mma16816(float (&c)[4], const uint32_t (&a)[4],
                                         uint32_t b0, uint32_t b1) {
    asm volatile(
        "mma.sync.aligned.m16n8k16.row.col.f32.f16.f16.f32 "
        "{%0,%1,%2,%3}, {%4,%5,%6,%7}, {%8,%9}, {%0,%1,%2,%3};\n"
        : "+f"(c[0]), "+f"(c[1]), "+f"(c[2]), "+f"(c[3])
        : "r"(a[0]), "r"(a[1]), "r"(a[2]), "r"(a[3]), "r"(b0), "r"(b1));
}

__device__ __forceinline__ void ldsm4(uint32_t (&r)[4], uint32_t saddr) {
    asm volatile(
        "ldmatrix.sync.aligned.m8n8.x4.shared.b16 {%0,%1,%2,%3}, [%4];\n"
        : "=r"(r[0]), "=r"(r[1]), "=r"(r[2]), "=r"(r[3]) : "r"(saddr));
}

__device__ __forceinline__ float sigmoidf_(float x) {
    return 1.0f / (1.0f + expf(-x));
}

__device__ __forceinline__ void cp16(uint32_t dst, const void* src) {
    asm volatile("cp.async.cg.shared.global [%0], [%1], 16;\n"
                 :: "r"(dst), "l"(src));
}
__device__ __forceinline__ void cp_commit() {
    asm volatile("cp.async.commit_group;\n");
}
template <int N>
__device__ __forceinline__ void cp_wait() {
    asm volatile("cp.async.wait_group %0;\n" :: "n"(N));
}

// Sense-reversing grid barrier. All NBLK blocks must be co-resident
// (guaranteed: 1 CTA/SM, NBLK=128 <= 148 SMs).
__device__ __forceinline__ void grid_sync() {
    __threadfence();           // release this thread's stores
    __syncthreads();
    if (threadIdx.x == 0) {
        unsigned gen = *(volatile unsigned*)&g_bar_gen;
        if (atomicAdd(&g_bar_cnt, 1u) == (unsigned)(NBLK - 1)) {
            g_bar_cnt = 0;
            __threadfence();
            *(volatile unsigned*)&g_bar_gen = gen + 1;
        } else {
            while (*(volatile unsigned*)&g_bar_gen == gen) __nanosleep(64);
        }
    }
    __syncthreads();
}

// ---------------------------------------------------------------------------
// Persistent-encoder step tile: block computes M=128 x 16 hidden cols of
// h_new. Weights already in smem (slab indices). A (h-prev fp16) streamed
// via cp.async double buffer (bufs {0,1} gh, {2,3} gi). 8 warps along M
// (warp tile m16 x 48 gate-cols).
// ---------------------------------------------------------------------------
template <bool HAS_GI, int IN_FEAT>
__device__ __forceinline__ void step_tile(
    uint32_t sbase, int m0, int h0col,
    const __half* __restrict__ Agh, const __half* __restrict__ Agi,
    int slabGH, int slabGI,
    const float* __restrict__ bih, const float* __restrict__ bhh,
    const float* __restrict__ WihS, const float* __restrict__ xrow, int xstride,
    const float* __restrict__ hprev, float* __restrict__ hout,
    __half* __restrict__ hout16) {

    const int tid  = threadIdx.x;
    const int lane = tid & 31;
    const int wid  = tid >> 5;        // 8 warps along M
    const int g4   = lane >> 2;
    const int t4   = lane & 3;
    const int lane15 = lane & 15;
    const int lhi8   = (lane >> 4) * 8;

    // cp.async staging: thread -> (row = tid>>1, 2 x 16B within 64B row chunk)
    const int srow = tid >> 1;
    const int sc0  = (tid & 1) * 2;
    const uint32_t adst0 = sbase + (uint32_t)((WTOT + srow * 40 + sc0 * 8) * 2);
    const __half* agsrc = Agh + (m0 + srow) * HDIM + sc0 * 8;
    const __half* aisrc = HAS_GI ? Agi + (m0 + srow) * HDIM + sc0 * 8 : nullptr;

    auto stage = [&](int ks) {
        const uint32_t d = adst0 + (uint32_t)((ks & 1) * ASTR * 2);
        const int ko = ks * 32;
        cp16(d, agsrc + ko);
        cp16(d + 16, agsrc + ko + 8);
        if (HAS_GI) {
            const uint32_t d2 = d + (uint32_t)(2 * ASTR * 2);
            cp16(d2, aisrc + ko);
            cp16(d2 + 16, aisrc + ko + 8);
        }
        cp_commit();
    };

    float acc_gh[3][2][4];
    float acc_gi[3][2][4];
#pragma unroll
    for (int g = 0; g < 3; g++)
#pragma unroll
        for (int nh = 0; nh < 2; nh++)
#pragma unroll
            for (int i = 0; i < 4; i++) {
                acc_gh[g][nh][i] = 0.f;
                if (HAS_GI) acc_gi[g][nh][i] = 0.f;
            }

    const uint32_t aoff = (uint32_t)(((wid * 16 + lane15) * 40 + lhi8) * 2);
    const uint32_t bgh  = sbase + (uint32_t)((slabGH * WSLAB + lane15 * WROWSTR + lhi8) * 2);
    const uint32_t bgi  = HAS_GI
        ? sbase + (uint32_t)((slabGI * WSLAB + lane15 * WROWSTR + lhi8) * 2) : 0;

    stage(0);
    for (int ks = 0; ks < 16; ks++) {
        if (ks < 15) { stage(ks + 1); cp_wait<1>(); }
        else         { cp_wait<0>(); }
        __syncthreads();

        const uint32_t abuf = sbase + (uint32_t)((WTOT + (ks & 1) * ASTR) * 2) + aoff;
        const uint32_t kofs = (uint32_t)(ks * 32 * 2);   // bytes: ks*32 halves

#pragma unroll
        for (int kstep = 0; kstep < 2; kstep++) {
            uint32_t a0[4], a1[4];
            ldsm4(a0, abuf + kstep * 32);
            if (HAS_GI) ldsm4(a1, abuf + (uint32_t)(2 * ASTR * 2) + kstep * 32);
#pragma unroll
            for (int g = 0; g < 3; g++) {
                uint32_t b[4];
                ldsm4(b, bgh + (uint32_t)(g * 16 * WROWSTR * 2) + kofs + kstep * 32);
                mma16816(acc_gh[g][0], a0, b[0], b[2]);
                mma16816(acc_gh[g][1], a0, b[1], b[3]);
                if (HAS_GI) {
                    uint32_t c[4];
                    ldsm4(c, bgi + (uint32_t)(g * 16 * WROWSTR * 2) + kofs + kstep * 32);
                    mma16816(acc_gi[g][0], a1, c[0], c[2]);
                    mma16816(acc_gi[g][1], a1, c[1], c[3]);
                }
            }
        }
        __syncthreads();
    }

    // ---- epilogue: gates fully in registers (known mma C layout) ----
    const int mbase = m0 + wid * 16 + g4;
    const int nbase = h0col + t4 * 2;

#pragma unroll
    for (int hm = 0; hm < 2; hm++) {
        const int row = mbase + hm * 8;
        float xv[IN_FEAT > 0 ? IN_FEAT : 1];
        if constexpr (!HAS_GI) {
#pragma unroll
            for (int i = 0; i < IN_FEAT; i++)
                xv[i] = xrow[row * xstride + i];
        }
#pragma unroll
        for (int nh = 0; nh < 2; nh++) {
            const int j0 = nbase + nh * 8;
            float2 hp = *(const float2*)(hprev + row * HDIM + j0);
            float2 ho;
#pragma unroll
            for (int cc = 0; cc < 2; cc++) {
                const int j = j0 + cc;
                const int ci = hm * 2 + cc;
                float gir, giz, gin;
                if constexpr (HAS_GI) {
                    gir = acc_gi[0][nh][ci] + bih[j];
                    giz = acc_gi[1][nh][ci] + bih[HDIM + j];
                    gin = acc_gi[2][nh][ci] + bih[2 * HDIM + j];
                } else {
                    gir = bih[j];
                    giz = bih[HDIM + j];
                    gin = bih[2 * HDIM + j];
                    const float* wr  = WihS + j * IN_FEAT;
                    const float* wz  = WihS + (HDIM + j) * IN_FEAT;
                    const float* wn_ = WihS + (2 * HDIM + j) * IN_FEAT;
#pragma unroll
                    for (int i = 0; i < IN_FEAT; i++) {
                        gir += xv[i] * wr[i];
                        giz += xv[i] * wz[i];
                        gin += xv[i] * wn_[i];
                    }
                }
                float ghr = acc_gh[0][nh][ci] + bhh[j];
                float ghz = acc_gh[1][nh][ci] + bhh[HDIM + j];
                float ghn = acc_gh[2][nh][ci] + bhh[2 * HDIM + j];
                float rg = sigmoidf_(gir + ghr);
                float zg = sigmoidf_(giz + ghz);
                float ng = tanhf(gin + rg * ghn);
                float hpv = cc ? hp.y : hp.x;
                float hv = (1.0f - zg) * ng + zg * hpv;
                if (cc) ho.y = hv; else ho.x = hv;
            }
            *(float2*)(hout + row * HDIM + j0) = ho;
            __half2 h2;
            h2.x = __float2half(ho.x);
            h2.y = __float2half(ho.y);
            *(__half2*)(hout16 + row * HDIM + j0) = h2;
        }
    }
}

// ---------------------------------------------------------------------------
// Persistent encoder: weight slabs loaded once, then 337 iterations with a
// grid barrier. Iter t: (phase A) h0[t] = GRU0(h0[t-1], x[t]);
//                       (phase B) h1[t-1] = GRU1(h1[t-2], h0[t-1]).
// Phases are independent within an iteration (1-step lag).
// ---------------------------------------------------------------------------
__global__ __launch_bounds__(256, 1)
void enc_persistent(const float* __restrict__ src,
                    const float* __restrict__ bih0, const float* __restrict__ bhh0,
                    const float* __restrict__ Wih0,
                    const float* __restrict__ bih1, const float* __restrict__ bhh1) {
    extern __shared__ __align__(16) __half dynsmem[];
    const uint32_t sbase = (uint32_t)__cvta_generic_to_shared(dynsmem);
    const int tid = threadIdx.x;
    const int m0 = (int)(blockIdx.x >> 5) * 128;      // 4 M tiles
    const int h0col = (int)(blockIdx.x & 31) * 16;    // 32 hidden-col tiles

    // Load this block's weight slabs (Whh0, Whh1, Wih1): 3 x 48 rows x 512
    {
        const __half* wsrc[3] = { g_Whh0, g_Whh1, g_Wih1 };
        for (int i = tid; i < 144 * 64; i += 256) {
            int rowid = i >> 6, c = i & 63;
            int mat = rowid / 48, r = rowid - mat * 48;
            int g = r >> 4, cc = r & 15;
            cp16(sbase + (uint32_t)((mat * WSLAB + r * WROWSTR + c * 8) * 2),
                 wsrc[mat] + (size_t)(g * HDIM + h0col + cc) * HDIM + c * 8);
        }
        cp_commit(); cp_wait<0>(); __syncthreads();
    }

    for (int t = 0; t <= TSTEPS; t++) {
        if (t < TSTEPS) {                         // layer0: h0[t]
            const int pw = t & 1, pr = pw ^ 1;
            step_tile<false, 8>(sbase, m0, h0col,
                g_h0_f16[pr], nullptr, 0, 0,
                bih0, bhh0, Wih0, src + t * 8, TSTEPS * 8,
                g_h0_f32[pr], g_h0_f32[pw], g_h0_f16[pw]);
        }
        if (t >= 1) {                             // layer1: h1[t-1]
            const int tt = t - 1;
            const int pw = tt & 1, pr = pw ^ 1;
            step_tile<true, 0>(sbase, m0, h0col,
                g_h1_f16[pr], g_h0_f16[tt & 1], 1, 2,
                bih1, bhh1, nullptr, nullptr, 0,
                g_h1_f32[pr], g_h1_f32[pw], g_h1_f16[pw]);
        }
        grid_sync();
    }
}

// ===========================================================================
// Decoder path (unchanged from R9): gru_block + dec kernels
// ===========================================================================
template <bool HAS_GI, int IN_FEAT, bool HAS_XFIRST, int BSTRIDE>
__device__ __forceinline__ void gru_block(
    __half* __restrict__ smem, int m0, int n0,
    const __half* __restrict__ Agh, const __half* __restrict__ Wgh,
    const __half* __restrict__ Agi, const __half* __restrict__ Wgi,
    const float* __restrict__ bih, const float* __restrict__ bhh,
    const float* __restrict__ WihS,
    const float* __restrict__ xrow, int xstride,
    const float* __restrict__ xfirst,
    const float* __restrict__ hprev, float* __restrict__ hout,
    __half* __restrict__ hout16) {

    const int tid  = threadIdx.x;
    const int lane = tid & 31;
    const int wid  = tid >> 5;
    const int wm   = wid >> 1;
    const int wn   = wid & 1;
    const int g4   = lane >> 2;
    const int t4   = lane & 3;

    const int r8 = tid >> 3;
    const int c8 = tid & 7;
    const uint32_t sbase = (uint32_t)__cvta_generic_to_shared(smem);
    const uint32_t sA  = sbase + (uint32_t)((r8 * 72 + c8 * 8) * 2);
    const uint32_t sB  = sbase + (uint32_t)((64 * 72 + r8 * 72 + c8 * 8) * 2);
    const __half* pA0   = Agh + (m0 + r8) * HDIM + c8 * 8;
    const __half* pB0_0 = Wgh + (0 * HDIM + n0 + r8) * HDIM + c8 * 8;
    const __half* pB0_1 = Wgh + (1 * HDIM + n0 + r8) * HDIM + c8 * 8;
    const __half* pB0_2 = Wgh + (2 * HDIM + n0 + r8) * HDIM + c8 * 8;

    auto stage = [&](int ks) {
        const uint32_t bo = (uint32_t)((ks & 1) * BSTRIDE * 2);
        const int ko = ks * 64;
        cp16(sA + bo, pA0 + ko);
        cp16(sA + bo + 32 * 72 * 2, pA0 + 32 * HDIM + ko);
        cp16(sB + bo, pB0_0 + ko);
        cp16(sB + bo + 32 * 72 * 2, pB0_1 + ko);
        cp16(sB + bo + 64 * 72 * 2, pB0_2 + ko);
        cp_commit();
    };

    float acc_gh[3][2][4];
#pragma unroll
    for (int g = 0; g < 3; g++)
#pragma unroll
        for (int nh = 0; nh < 2; nh++)
#pragma unroll
            for (int i = 0; i < 4; i++) acc_gh[g][nh][i] = 0.f;

    const int lane15 = lane & 15;
    const int lhi8   = (lane >> 4) * 8;
    const uint32_t aoff = (uint32_t)(((wm * 16 + lane15) * 72 + lhi8) * 2);
    uint32_t boff[3];
#pragma unroll
    for (int g = 0; g < 3; g++)
        boff[g] = (uint32_t)(((64 + g * 32 + wn * 16 + lane15) * 72 + lhi8) * 2);

    stage(0);
    for (int ks = 0; ks < 8; ks++) {
        if (ks < 7) { stage(ks + 1); cp_wait<1>(); }
        else        { cp_wait<0>(); }
        __syncthreads();
        const uint32_t base = sbase + (uint32_t)((ks & 1) * BSTRIDE * 2);
#pragma unroll
        for (int kk = 0; kk < 64; kk += 16) {
            uint32_t a0[4];
            ldsm4(a0, base + aoff + kk * 2);
#pragma unroll
            for (int g = 0; g < 3; g++) {
                uint32_t b[4];
                ldsm4(b, base + boff[g] + kk * 2);
                mma16816(acc_gh[g][0], a0, b[0], b[2]);
                mma16816(acc_gh[g][1], a0, b[1], b[3]);
            }
        }
        __syncthreads();
    }

    const int mbase = m0 + wm * 16 + g4;
    const int nbase = n0 + wn * 16 + t4 * 2;

#pragma unroll
    for (int hm = 0; hm < 2; hm++) {
        const int row = mbase + hm * 8;
        float xv[IN_FEAT > 0 ? IN_FEAT : 1];
        if constexpr (HAS_XFIRST) {
            xv[0] = xfirst[row];
#pragma unroll
            for (int i = 1; i < IN_FEAT; i++)
                xv[i] = xrow[row * xstride + i - 1];
        } else {
#pragma unroll
            for (int i = 0; i < IN_FEAT; i++)
                xv[i] = xrow[row * xstride + i];
        }
#pragma unroll
        for (int nh = 0; nh < 2; nh++) {
            const int j0 = nbase + nh * 8;
            float2 hp = *(const float2*)(hprev + row * HDIM + j0);
            float2 ho;
#pragma unroll
            for (int cc = 0; cc < 2; cc++) {
                const int j = j0 + cc;
                const int ci = hm * 2 + cc;
                float gir = bih[j];
                float giz = bih[HDIM + j];
                float gin = bih[2 * HDIM + j];
                const float* wr  = WihS + j * IN_FEAT;
                const float* wz  = WihS + (HDIM + j) * IN_FEAT;
                const float* wn_ = WihS + (2 * HDIM + j) * IN_FEAT;
#pragma unroll
                for (int i = 0; i < IN_FEAT; i++) {
                    gir += xv[i] * wr[i];
                    giz += xv[i] * wz[i];
                    gin += xv[i] * wn_[i];
                }
                float ghr = acc_gh[0][nh][ci] + bhh[j];
                float ghz = acc_gh[1][nh][ci] + bhh[HDIM + j];
                float ghn = acc_gh[2][nh][ci] + bhh[2 * HDIM + j];
                float rg = sigmoidf_(gir + ghr);
                float zg = sigmoidf_(giz + ghz);
                float ng = tanhf(gin + rg * ghn);
                float hpv = cc ? hp.y : hp.x;
                float hv = (1.0f - zg) * ng + zg * hpv;
                if (cc) ho.y = hv; else ho.x = hv;
            }
            *(float2*)(hout + row * HDIM + j0) = ho;
            __half2 h2;
            h2.x = __float2half(ho.x);
            h2.y = __float2half(ho.y);
            *(__half2*)(hout16 + row * HDIM + j0) = h2;
        }
    }
}

#define DEC_BSTRIDE (160 * 72)
#define DEC_SMEM    (2 * DEC_BSTRIDE * 2)   // 46080 bytes

__global__ __launch_bounds__(256, 2)
void dec_step_kernel(int s, const float* __restrict__ tf,
                     const float* __restrict__ cbih, const float* __restrict__ cbhh,
                     const float* __restrict__ cWih) {
    extern __shared__ __align__(16) __half dynsmem2[];
    const int bid = blockIdx.x;
    const int m0 = (bid >> 4) * 64;
    const int n0 = (bid & 15) * 32;
    const int pr = s & 1, pw = (s + 1) & 1;
    gru_block<false, 9, true, DEC_BSTRIDE>(dynsmem2, m0, n0,
        g_hd_f16[pr], g_cWhh, nullptr, nullptr,
        cbih, cbhh, cWih, tf + s * 8, HORIZON * 8, g_lastv,
        g_hd_f32[pr], g_hd_f32[pw], g_hd_f16[pw]);
}

__global__ __launch_bounds__(256)
void fc_kernel(int s, const float* __restrict__ fcW, const float* __restrict__ fcb,
               float* __restrict__ out) {
    const int b = blockIdx.x * 8 + (threadIdx.x >> 5);
    const int lane = threadIdx.x & 31;
    const float* h = g_hd_f32[(s + 1) & 1] + b * HDIM;
    float sum = 0.f;
#pragma unroll
    for (int k = lane; k < HDIM; k += 32) sum += h[k] * fcW[k];
#pragma unroll
    for (int o = 16; o; o >>= 1) sum += __shfl_xor_sync(0xffffffffu, sum, o);
    if (lane == 0) {
        float p = sum + fcb[0];
        out[b * HORIZON + s] = p;
        g_lastv[b] = p;
    }
}

__global__ __launch_bounds__(256)
void dec0_kernel(const float* __restrict__ W, const float* __restrict__ bias) {
    __shared__ float As[64][17];
    __shared__ float Ws[64][17];
    const float* A = g_h1_f32[(TSTEPS - 1) & 1];
    const int m0 = blockIdx.y * 64, n0 = blockIdx.x * 64;
    const int tx = threadIdx.x & 15, ty = threadIdx.x >> 4;
    float acc[4][4] = {};
    for (int k0 = 0; k0 < HDIM; k0 += 16) {
#pragma unroll
        for (int i = 0; i < 4; i++) {
            int idx = threadIdx.x + i * 256;
            int r = idx >> 4, c = idx & 15;
            As[r][c] = A[(m0 + r) * HDIM + k0 + c];
            Ws[r][c] = W[(n0 + r) * HDIM + k0 + c];
        }
        __syncthreads();
#pragma unroll
        for (int kk = 0; kk < 16; kk++) {
            float a[4], w[4];
#pragma unroll
            for (int i = 0; i < 4; i++) { a[i] = As[ty * 4 + i][kk]; w[i] = Ws[tx * 4 + i][kk]; }
#pragma unroll
            for (int i = 0; i < 4; i++)
#pragma unroll
                for (int j = 0; j < 4; j++) acc[i][j] += a[i] * w[j];
        }
        __syncthreads();
    }
#pragma unroll
    for (int i = 0; i < 4; i++)
#pragma unroll
        for (int j = 0; j < 4; j++) {
            int m = m0 + ty * 4 + i, n = n0 + tx * 4 + j;
            float v = acc[i][j] + bias[n];
            g_hd_f32[0][m * HDIM + n] = v;
            g_hd_f16[0][m * HDIM + n] = __float2half(v);
        }
}

// ---------------------------------------------------------------------------
// setup kernels
// ---------------------------------------------------------------------------
__global__ void convert_weights_kernel(const float* __restrict__ Whh0,
                                       const float* __restrict__ Wih1,
                                       const float* __restrict__ Whh1,
                                       const float* __restrict__ cWhh) {
    int i = blockIdx.x * blockDim.x + threadIdx.x;
    if (i < G3H * HDIM) {
        g_Whh0[i] = __float2half(Whh0[i]);
        g_Wih1[i] = __float2half(Wih1[i]);
        g_Whh1[i] = __float2half(Whh1[i]);
        g_cWhh[i] = __float2half(cWhh[i]);
    }
}

__global__ void init_kernel(const float* __restrict__ src) {
    int i = blockIdx.x * blockDim.x + threadIdx.x;
    if (i < BATCH * HDIM) {
        g_h0_f32[1][i] = 0.f;
        g_h1_f32[1][i] = 0.f;
        g_h0_f16[1][i] = __float2half(0.f);
        g_h1_f16[1][i] = __float2half(0.f);
    }
    if (i < BATCH) g_lastv[i] = src[i * (TSTEPS * 8) + (TSTEPS - 1) * 8];
    if (i == 0) { g_bar_cnt = 0; g_bar_gen = 0; }
}

// ---------------------------------------------------------------------------
extern "C" void kernel_launch(void* const* d_in, const int* in_sizes, int n_in,
                              void* d_out, int out_size) {
    const float* src   = (const float*)d_in[0];
    const float* tf    = (const float*)d_in[1];
    const float* Wih0  = (const float*)d_in[2];
    const float* Whh0  = (const float*)d_in[3];
    const float* bih0  = (const float*)d_in[4];
    const float* bhh0  = (const float*)d_in[5];
    const float* Wih1  = (const float*)d_in[6];
    const float* Whh1  = (const float*)d_in[7];
    const float* bih1  = (const float*)d_in[8];
    const float* bhh1  = (const float*)d_in[9];
    const float* dec0W = (const float*)d_in[10];
    const float* dec0b = (const float*)d_in[11];
    const float* cWih  = (const float*)d_in[12];
    const float* cWhh  = (const float*)d_in[13];
    const float* cbih  = (const float*)d_in[14];
    const float* cbhh  = (const float*)d_in[15];
    const float* fcW   = (const float*)d_in[16];
    const float* fcb   = (const float*)d_in[17];
    float* out = (float*)d_out;

    cudaFuncSetAttribute(enc_persistent,
                         cudaFuncAttributeMaxDynamicSharedMemorySize, PSMEM);
    cudaFuncSetAttribute(dec_step_kernel,
                         cudaFuncAttributeMaxDynamicSharedMemorySize, DEC_SMEM);

    convert_weights_kernel<<<(G3H * HDIM + 255) / 256, 256>>>(Whh0, Wih1, Whh1, cWhh);
    init_kernel<<<(BATCH * HDIM + 255) / 256, 256>>>(src);

    // Whole encoder in ONE persistent launch
    enc_persistent<<<NBLK, 256, PSMEM>>>(src, bih0, bhh0, Wih0, bih1, bhh1);

    // Decoder init + 48 steps
    dec0_kernel<<<dim3(8, 8), 256>>>(dec0W, dec0b);
    for (int s = 0; s < HORIZON; s++) {
        dec_step_kernel<<<128, 256, DEC_SMEM>>>(s, tf, cbih, cbhh, cWih);
        fc_kernel<<<64, 256>>>(s, fcW, fcb, out);
    }
}

// round 12
// speedup vs baseline: 1.0034x; 1.0034x over previous
#include <cuda_runtime.h>
#include <cuda_fp16.h>
#include <cstdint>

// ---------------------------------------------------------------------------
// Seq2SeqForecast: 2-layer GRU encoder (B=512, T=336, H=512) + 48-step GRU
// decoder with scalar head.
//
// R11: persistent encoder v2 (R10 regressed: depth-1 pipeline, serial phases,
// per-iter epilogue LDG storm).
//  * 3-stage cp.async ring for A tiles, ONE __syncthreads per chunk.
//  * Unified 32-chunk schedule per iteration spanning layer0+layer1 — the
//    prefetch pipeline never drains at the phase boundary.
//  * X = h0[t-1] tile streamed once, consumed by layer0-gh AND layer1-gi.
//  * Wih0 slab + all biases cached in smem at prologue (epilogue = LDS only).
// Decoder unchanged (R9 path).
// ---------------------------------------------------------------------------

#define HDIM    512
#define BATCH   512
#define TSTEPS  336
#define HORIZON 48
#define G3H     (3 * HDIM)

#define NBLK    128
#define WROWSTR 520                     // halves per weight row (LDSM conflict-free pad)
#define WSLAB   (48 * WROWSTR)          // one matrix slab: 3 gates x 16 cols
#define WTOT    (3 * WSLAB)             // Whh0, Whh1, Wih1  (74880 halves)
#define ASTRC   (128 * 40)              // one stream chunk: 128 rows x 32(+8 pad) halves
#define RINGH   (3 * 2 * ASTRC)         // 3 stages x 2 streams (30720 halves)
#define EPIF    576                     // epilogue consts (floats)
#define PSMEM   ((WTOT + RINGH) * 2 + EPIF * 4)   // 213504 bytes

// fp16 weight copies
__device__ __half g_Whh0[G3H * HDIM];
__device__ __half g_Wih1[G3H * HDIM];
__device__ __half g_Whh1[G3H * HDIM];
__device__ __half g_cWhh[G3H * HDIM];

// hidden-state ping-pong buffers (fp32 master + fp16 shadow for MMA)
__device__ float  g_h0_f32[2][BATCH * HDIM];
__device__ __half g_h0_f16[2][BATCH * HDIM];
__device__ float  g_h1_f32[2][BATCH * HDIM];
__device__ __half g_h1_f16[2][BATCH * HDIM];
__device__ float  g_hd_f32[2][BATCH * HDIM];
__device__ __half g_hd_f16[2][BATCH * HDIM];
__device__ float  g_lastv[BATCH];

// grid barrier state
__device__ unsigned g_bar_cnt;
__device__ unsigned g_bar_gen;

// ---------------------------------------------------------------------------
// helpers
// ---------------------------------------------------------------------------
__device__ __forceinline__ void mma16816(float (&c)[4], const uint32_t (&a)[4],
                                         uint32_t b0, uint32_t b1) {
    asm volatile(
        "mma.sync.aligned.m16n8k16.row.col.f32.f16.f16.f32 "
        "{%0,%1,%2,%3}, {%4,%5,%6,%7}, {%8,%9}, {%0,%1,%2,%3};\n"
        : "+f"(c[0]), "+f"(c[1]), "+f"(c[2]), "+f"(c[3])
        : "r"(a[0]), "r"(a[1]), "r"(a[2]), "r"(a[3]), "r"(b0), "r"(b1));
}

__device__ __forceinline__ void ldsm4(uint32_t (&r)[4], uint32_t saddr) {
    asm volatile(
        "ldmatrix.sync.aligned.m8n8.x4.shared.b16 {%0,%1,%2,%3}, [%4];\n"
        : "=r"(r[0]), "=r"(r[1]), "=r"(r[2]), "=r"(r[3]) : "r"(saddr));
}

__device__ __forceinline__ float sigmoidf_(float x) {
    return 1.0f / (1.0f + expf(-x));
}

__device__ __forceinline__ void cp16(uint32_t dst, const void* src) {
    asm volatile("cp.async.cg.shared.global [%0], [%1], 16;\n"
                 :: "r"(dst), "l"(src));
}
__device__ __forceinline__ void cp_commit() {
    asm volatile("cp.async.commit_group;\n");
}
template <int N>
__device__ __forceinline__ void cp_wait() {
    asm volatile("cp.async.wait_group %0;\n" :: "n"(N));
}

__device__ __forceinline__ float dot8(const float (&x)[8], const float* w) {
    const float4* w4 = (const float4*)w;
    float4 wa = w4[0], wb = w4[1];
    return x[0]*wa.x + x[1]*wa.y + x[2]*wa.z + x[3]*wa.w
         + x[4]*wb.x + x[5]*wb.y + x[6]*wb.z + x[7]*wb.w;
}

// Sense-reversing grid barrier (all NBLK=128 blocks co-resident: 1 CTA/SM).
__device__ __forceinline__ void grid_sync() {
    __threadfence();
    __syncthreads();
    if (threadIdx.x == 0) {
        unsigned gen = *(volatile unsigned*)&g_bar_gen;
        if (atomicAdd(&g_bar_cnt, 1u) == (unsigned)(NBLK - 1)) {
            g_bar_cnt = 0;
            __threadfence();
            *(volatile unsigned*)&g_bar_gen = gen + 1;
        } else {
            while (*(volatile unsigned*)&g_bar_gen == gen) __nanosleep(64);
        }
    }
    __syncthreads();
}

// ---------------------------------------------------------------------------
// Persistent encoder. Block owns M=128 batch rows x 16 hidden cols.
// smem: [Whh0 | Whh1 | Wih1 slabs][3-stage A ring: (X,Y) pairs][epi consts]
// Iter t: slots 0..15  -> layer0 gh accumulate (X = h0[t-1], Whh0)
//         slots 16..31 -> layer1 gh (Y = h1[t-2], Whh1) + gi (X, Wih1)
// ---------------------------------------------------------------------------
__global__ __launch_bounds__(256, 1)
void enc_persistent(const float* __restrict__ src,
                    const float* __restrict__ bih0, const float* __restrict__ bhh0,
                    const float* __restrict__ Wih0,
                    const float* __restrict__ bih1, const float* __restrict__ bhh1) {
    extern __shared__ __align__(16) __half dynsmem[];
    const uint32_t sbase = (uint32_t)__cvta_generic_to_shared(dynsmem);
    float* epi = (float*)(dynsmem + WTOT + RINGH);   // [48*8 W0][48 bih0][48 bhh0][48 bih1][48 bhh1]

    const int tid  = threadIdx.x;
    const int lane = tid & 31;
    const int wid  = tid >> 5;            // 8 warps along M
    const int g4   = lane >> 2;
    const int t4   = lane & 3;
    const int lane15 = lane & 15;
    const int lhi8   = (lane >> 4) * 8;

    const int m0    = (int)(blockIdx.x >> 5) * 128;
    const int h0col = (int)(blockIdx.x & 31) * 16;

    // ---- prologue: weight slabs (cp.async) + epilogue consts (LDG/STS) ----
    {
        const __half* wsrc[3] = { g_Whh0, g_Whh1, g_Wih1 };
        for (int i = tid; i < 144 * 64; i += 256) {
            int rowid = i >> 6, c = i & 63;
            int mat = rowid / 48, r = rowid - mat * 48;
            int g = r >> 4, cc = r & 15;
            cp16(sbase + (uint32_t)((mat * WSLAB + r * WROWSTR + c * 8) * 2),
                 wsrc[mat] + (size_t)(g * HDIM + h0col + cc) * HDIM + c * 8);
        }
        for (int i = tid; i < 384; i += 256) {
            int gc = i >> 3, ii = i & 7;
            int g = gc >> 4, jc = gc & 15;
            epi[i] = Wih0[(g * HDIM + h0col + jc) * 8 + ii];
        }
        for (int i = tid; i < 48; i += 256) {
            int g = i >> 4, jc = i & 15;
            int col = g * HDIM + h0col + jc;
            epi[384 + i] = bih0[col];
            epi[432 + i] = bhh0[col];
            epi[480 + i] = bih1[col];
            epi[528 + i] = bhh1[col];
        }
        cp_commit(); cp_wait<0>(); __syncthreads();
    }

    // staging thread mapping: each thread copies 16 halves (2x16B) of one row
    const int srow = tid >> 1;
    const int sc16 = (tid & 1) * 16;      // halves offset within 32-half chunk

    // ldmatrix thread-constant offsets
    const uint32_t aoff = (uint32_t)(((wid * 16 + lane15) * 40 + lhi8) * 2);
    const uint32_t bW0  = sbase + (uint32_t)((lane15 * WROWSTR + lhi8) * 2);
    const uint32_t bW1  = bW0 + (uint32_t)(WSLAB * 2);
    const uint32_t bW2  = bW0 + (uint32_t)(2 * WSLAB * 2);

    for (int t = 0; t <= TSTEPS; t++) {
        const bool doA = (t < TSTEPS);
        const bool doB = (t >= 1);
        const int sBeg = doA ? 0 : 16;
        const int sEnd = doB ? 32 : 16;

        const __half* Xp = g_h0_f16[(t + 1) & 1] + (size_t)(m0 + srow) * HDIM + sc16;
        const __half* Yp = g_h1_f16[t & 1]       + (size_t)(m0 + srow) * HDIM + sc16;

        auto stage = [&](int s) {
            const int chunk = s & 15;
            const uint32_t d = sbase +
                (uint32_t)((WTOT + (s % 3) * (2 * ASTRC) + srow * 40 + sc16) * 2);
            const __half* xs = Xp + chunk * 32;
            cp16(d, xs); cp16(d + 16, xs + 8);
            if (s >= 16) {
                const __half* ys = Yp + chunk * 32;
                const uint32_t d2 = d + (uint32_t)(ASTRC * 2);
                cp16(d2, ys); cp16(d2 + 16, ys + 8);
            }
            cp_commit();
        };

        float accA[3][2][4];
        float accBgh[3][2][4];
        float accBgi[3][2][4];
#pragma unroll
        for (int g = 0; g < 3; g++)
#pragma unroll
            for (int nh = 0; nh < 2; nh++)
#pragma unroll
                for (int i = 0; i < 4; i++) {
                    accA[g][nh][i] = 0.f;
                    accBgh[g][nh][i] = 0.f;
                    accBgi[g][nh][i] = 0.f;
                }

        stage(sBeg);
        stage(sBeg + 1);

        for (int s = sBeg; s < sEnd; s++) {
            if (s < sEnd - 1) cp_wait<1>(); else cp_wait<0>();
            __syncthreads();
            if (s + 2 < sEnd) stage(s + 2);

            const int chunk = s & 15;
            const uint32_t xbuf = sbase +
                (uint32_t)((WTOT + (s % 3) * (2 * ASTRC)) * 2) + aoff;
            const uint32_t kb = (uint32_t)(chunk * 64);   // chunk*32 halves in bytes

            if (s < 16) {
#pragma unroll
                for (int kstep = 0; kstep < 2; kstep++) {
                    uint32_t a[4];
                    ldsm4(a, xbuf + kstep * 32);
#pragma unroll
                    for (int g = 0; g < 3; g++) {
                        uint32_t b[4];
                        ldsm4(b, bW0 + (uint32_t)(g * 16 * WROWSTR * 2) + kb + kstep * 32);
                        mma16816(accA[g][0], a, b[0], b[2]);
                        mma16816(accA[g][1], a, b[1], b[3]);
                    }
                }
                if (chunk == 15) {
                    // ---- layer0 epilogue: h0[t] ----
                    const float* hprev = g_h0_f32[(t + 1) & 1];
                    float*  hout  = g_h0_f32[t & 1];
                    __half* h16   = g_h0_f16[t & 1];
#pragma unroll
                    for (int hm = 0; hm < 2; hm++) {
                        const int row = m0 + wid * 16 + g4 + hm * 8;
                        const float4* xp4 =
                            (const float4*)(src + ((size_t)row * TSTEPS + t) * 8);
                        float4 xa = xp4[0], xb = xp4[1];
                        float xv[8] = {xa.x, xa.y, xa.z, xa.w, xb.x, xb.y, xb.z, xb.w};
#pragma unroll
                        for (int nh = 0; nh < 2; nh++) {
                            const int jl = t4 * 2 + nh * 8;
                            const int j  = h0col + jl;
                            float2 hp = *(const float2*)(hprev + (size_t)row * HDIM + j);
                            float2 ho;
#pragma unroll
                            for (int cc = 0; cc < 2; cc++) {
                                const int jlc = jl + cc;
                                const int ci  = hm * 2 + cc;
                                float gir = epi[384 + jlc]      + dot8(xv, epi + jlc * 8);
                                float giz = epi[384 + 16 + jlc] + dot8(xv, epi + (16 + jlc) * 8);
                                float gin = epi[384 + 32 + jlc] + dot8(xv, epi + (32 + jlc) * 8);
                                float ghr = accA[0][nh][ci] + epi[432 + jlc];
                                float ghz = accA[1][nh][ci] + epi[432 + 16 + jlc];
                                float ghn = accA[2][nh][ci] + epi[432 + 32 + jlc];
                                float rg = sigmoidf_(gir + ghr);
                                float zg = sigmoidf_(giz + ghz);
                                float ng = tanhf(gin + rg * ghn);
                                float hpv = cc ? hp.y : hp.x;
                                float hv = (1.0f - zg) * ng + zg * hpv;
                                if (cc) ho.y = hv; else ho.x = hv;
                            }
                            *(float2*)(hout + (size_t)row * HDIM + j) = ho;
                            __half2 h2;
                            h2.x = __float2half(ho.x);
                            h2.y = __float2half(ho.y);
                            *(__half2*)(h16 + (size_t)row * HDIM + j) = h2;
                        }
                    }
                }
            } else {
                const uint32_t ybuf = xbuf + (uint32_t)(ASTRC * 2);
#pragma unroll
                for (int kstep = 0; kstep < 2; kstep++) {
                    uint32_t agh[4], agi[4];
                    ldsm4(agh, ybuf + kstep * 32);
                    ldsm4(agi, xbuf + kstep * 32);
#pragma unroll
                    for (int g = 0; g < 3; g++) {
                        uint32_t b[4], c[4];
                        ldsm4(b, bW1 + (uint32_t)(g * 16 * WROWSTR * 2) + kb + kstep * 32);
                        mma16816(accBgh[g][0], agh, b[0], b[2]);
                        mma16816(accBgh[g][1], agh, b[1], b[3]);
                        ldsm4(c, bW2 + (uint32_t)(g * 16 * WROWSTR * 2) + kb + kstep * 32);
                        mma16816(accBgi[g][0], agi, c[0], c[2]);
                        mma16816(accBgi[g][1], agi, c[1], c[3]);
                    }
                }
            }
        }

        if (doB) {
            // ---- layer1 epilogue: h1[t-1] ----
            const float* hprev = g_h1_f32[t & 1];
            float*  hout  = g_h1_f32[(t + 1) & 1];
            __half* h16   = g_h1_f16[(t + 1) & 1];
#pragma unroll
            for (int hm = 0; hm < 2; hm++) {
                const int row = m0 + wid * 16 + g4 + hm * 8;
#pragma unroll
                for (int nh = 0; nh < 2; nh++) {
                    const int jl = t4 * 2 + nh * 8;
                    const int j  = h0col + jl;
                    float2 hp = *(const float2*)(hprev + (size_t)row * HDIM + j);
                    float2 ho;
#pragma unroll
                    for (int cc = 0; cc < 2; cc++) {
                        const int jlc = jl + cc;
                        const int ci  = hm * 2 + cc;
                        float gir = accBgi[0][nh][ci] + epi[480 + jlc];
                        float giz = accBgi[1][nh][ci] + epi[480 + 16 + jlc];
                        float gin = accBgi[2][nh][ci] + epi[480 + 32 + jlc];
                        float ghr = accBgh[0][nh][ci] + epi[528 + jlc];
                        float ghz = accBgh[1][nh][ci] + epi[528 + 16 + jlc];
                        float ghn = accBgh[2][nh][ci] + epi[528 + 32 + jlc];
                        float rg = sigmoidf_(gir + ghr);
                        float zg = sigmoidf_(giz + ghz);
                        float ng = tanhf(gin + rg * ghn);
                        float hpv = cc ? hp.y : hp.x;
                        float hv = (1.0f - zg) * ng + zg * hpv;
                        if (cc) ho.y = hv; else ho.x = hv;
                    }
                    *(float2*)(hout + (size_t)row * HDIM + j) = ho;
                    __half2 h2;
                    h2.x = __float2half(ho.x);
                    h2.y = __float2half(ho.y);
                    *(__half2*)(h16 + (size_t)row * HDIM + j) = h2;
                }
            }
        }

        grid_sync();
    }
}

// ===========================================================================
// Decoder path (R9): gru_block + dec kernels
// ===========================================================================
template <int IN_FEAT, int BSTRIDE>
__device__ __forceinline__ void gru_block(
    __half* __restrict__ smem, int m0, int n0,
    const __half* __restrict__ Agh, const __half* __restrict__ Wgh,
    const float* __restrict__ bih, const float* __restrict__ bhh,
    const float* __restrict__ WihS,
    const float* __restrict__ xrow, int xstride,
    const float* __restrict__ xfirst,
    const float* __restrict__ hprev, float* __restrict__ hout,
    __half* __restrict__ hout16) {

    const int tid  = threadIdx.x;
    const int lane = tid & 31;
    const int wid  = tid >> 5;
    const int wm   = wid >> 1;
    const int wn   = wid & 1;
    const int g4   = lane >> 2;
    const int t4   = lane & 3;

    const int r8 = tid >> 3;
    const int c8 = tid & 7;
    const uint32_t sbase = (uint32_t)__cvta_generic_to_shared(smem);
    const uint32_t sA  = sbase + (uint32_t)((r8 * 72 + c8 * 8) * 2);
    const uint32_t sB  = sbase + (uint32_t)((64 * 72 + r8 * 72 + c8 * 8) * 2);
    const __half* pA0   = Agh + (m0 + r8) * HDIM + c8 * 8;
    const __half* pB0_0 = Wgh + (0 * HDIM + n0 + r8) * HDIM + c8 * 8;
    const __half* pB0_1 = Wgh + (1 * HDIM + n0 + r8) * HDIM + c8 * 8;
    const __half* pB0_2 = Wgh + (2 * HDIM + n0 + r8) * HDIM + c8 * 8;

    auto stage = [&](int ks) {
        const uint32_t bo = (uint32_t)((ks & 1) * BSTRIDE * 2);
        const int ko = ks * 64;
        cp16(sA + bo, pA0 + ko);
        cp16(sA + bo + 32 * 72 * 2, pA0 + 32 * HDIM + ko);
        cp16(sB + bo, pB0_0 + ko);
        cp16(sB + bo + 32 * 72 * 2, pB0_1 + ko);
        cp16(sB + bo + 64 * 72 * 2, pB0_2 + ko);
        cp_commit();
    };

    float acc_gh[3][2][4];
#pragma unroll
    for (int g = 0; g < 3; g++)
#pragma unroll
        for (int nh = 0; nh < 2; nh++)
#pragma unroll
            for (int i = 0; i < 4; i++) acc_gh[g][nh][i] = 0.f;

    const int lane15 = lane & 15;
    const int lhi8   = (lane >> 4) * 8;
    const uint32_t aoff = (uint32_t)(((wm * 16 + lane15) * 72 + lhi8) * 2);
    uint32_t boff[3];
#pragma unroll
    for (int g = 0; g < 3; g++)
        boff[g] = (uint32_t)(((64 + g * 32 + wn * 16 + lane15) * 72 + lhi8) * 2);

    stage(0);
    for (int ks = 0; ks < 8; ks++) {
        if (ks < 7) { stage(ks + 1); cp_wait<1>(); }
        else        { cp_wait<0>(); }
        __syncthreads();
        const uint32_t base = sbase + (uint32_t)((ks & 1) * BSTRIDE * 2);
#pragma unroll
        for (int kk = 0; kk < 64; kk += 16) {
            uint32_t a0[4];
            ldsm4(a0, base + aoff + kk * 2);
#pragma unroll
            for (int g = 0; g < 3; g++) {
                uint32_t b[4];
                ldsm4(b, base + boff[g] + kk * 2);
                mma16816(acc_gh[g][0], a0, b[0], b[2]);
                mma16816(acc_gh[g][1], a0, b[1], b[3]);
            }
        }
        __syncthreads();
    }

    const int mbase = m0 + wm * 16 + g4;
    const int nbase = n0 + wn * 16 + t4 * 2;

#pragma unroll
    for (int hm = 0; hm < 2; hm++) {
        const int row = mbase + hm * 8;
        float xv[IN_FEAT];
        xv[0] = xfirst[row];
#pragma unroll
        for (int i = 1; i < IN_FEAT; i++)
            xv[i] = xrow[row * xstride + i - 1];
#pragma unroll
        for (int nh = 0; nh < 2; nh++) {
            const int j0 = nbase + nh * 8;
            float2 hp = *(const float2*)(hprev + row * HDIM + j0);
            float2 ho;
#pragma unroll
            for (int cc = 0; cc < 2; cc++) {
                const int j = j0 + cc;
                const int ci = hm * 2 + cc;
                float gir = bih[j];
                float giz = bih[HDIM + j];
                float gin = bih[2 * HDIM + j];
                const float* wr  = WihS + j * IN_FEAT;
                const float* wz  = WihS + (HDIM + j) * IN_FEAT;
                const float* wn_ = WihS + (2 * HDIM + j) * IN_FEAT;
#pragma unroll
                for (int i = 0; i < IN_FEAT; i++) {
                    gir += xv[i] * wr[i];
                    giz += xv[i] * wz[i];
                    gin += xv[i] * wn_[i];
                }
                float ghr = acc_gh[0][nh][ci] + bhh[j];
                float ghz = acc_gh[1][nh][ci] + bhh[HDIM + j];
                float ghn = acc_gh[2][nh][ci] + bhh[2 * HDIM + j];
                float rg = sigmoidf_(gir + ghr);
                float zg = sigmoidf_(giz + ghz);
                float ng = tanhf(gin + rg * ghn);
                float hpv = cc ? hp.y : hp.x;
                float hv = (1.0f - zg) * ng + zg * hpv;
                if (cc) ho.y = hv; else ho.x = hv;
            }
            *(float2*)(hout + row * HDIM + j0) = ho;
            __half2 h2;
            h2.x = __float2half(ho.x);
            h2.y = __float2half(ho.y);
            *(__half2*)(hout16 + row * HDIM + j0) = h2;
        }
    }
}

#define DEC_BSTRIDE (160 * 72)
#define DEC_SMEM    (2 * DEC_BSTRIDE * 2)

__global__ __launch_bounds__(256, 2)
void dec_step_kernel(int s, const float* __restrict__ tf,
                     const float* __restrict__ cbih, const float* __restrict__ cbhh,
                     const float* __restrict__ cWih) {
    extern __shared__ __align__(16) __half dynsmem2[];
    const int bid = blockIdx.x;
    const int m0 = (bid >> 4) * 64;
    const int n0 = (bid & 15) * 32;
    const int pr = s & 1, pw = (s + 1) & 1;
    gru_block<9, DEC_BSTRIDE>(dynsmem2, m0, n0,
        g_hd_f16[pr], g_cWhh,
        cbih, cbhh, cWih, tf + s * 8, HORIZON * 8, g_lastv,
        g_hd_f32[pr], g_hd_f32[pw], g_hd_f16[pw]);
}

__global__ __launch_bounds__(256)
void fc_kernel(int s, const float* __restrict__ fcW, const float* __restrict__ fcb,
               float* __restrict__ out) {
    const int b = blockIdx.x * 8 + (threadIdx.x >> 5);
    const int lane = threadIdx.x & 31;
    const float* h = g_hd_f32[(s + 1) & 1] + b * HDIM;
    float sum = 0.f;
#pragma unroll
    for (int k = lane; k < HDIM; k += 32) sum += h[k] * fcW[k];
#pragma unroll
    for (int o = 16; o; o >>= 1) sum += __shfl_xor_sync(0xffffffffu, sum, o);
    if (lane == 0) {
        float p = sum + fcb[0];
        out[b * HORIZON + s] = p;
        g_lastv[b] = p;
    }
}

__global__ __launch_bounds__(256)
void dec0_kernel(const float* __restrict__ W, const float* __restrict__ bias) {
    __shared__ float As[64][17];
    __shared__ float Ws[64][17];
    const float* A = g_h1_f32[(TSTEPS - 1) & 1];
    const int m0 = blockIdx.y * 64, n0 = blockIdx.x * 64;
    const int tx = threadIdx.x & 15, ty = threadIdx.x >> 4;
    float acc[4][4] = {};
    for (int k0 = 0; k0 < HDIM; k0 += 16) {
#pragma unroll
        for (int i = 0; i < 4; i++) {
            int idx = threadIdx.x + i * 256;
            int r = idx >> 4, c = idx & 15;
            As[r][c] = A[(m0 + r) * HDIM + k0 + c];
            Ws[r][c] = W[(n0 + r) * HDIM + k0 + c];
        }
        __syncthreads();
#pragma unroll
        for (int kk = 0; kk < 16; kk++) {
            float a[4], w[4];
#pragma unroll
            for (int i = 0; i < 4; i++) { a[i] = As[ty * 4 + i][kk]; w[i] = Ws[tx * 4 + i][kk]; }
#pragma unroll
            for (int i = 0; i < 4; i++)
#pragma unroll
                for (int j = 0; j < 4; j++) acc[i][j] += a[i] * w[j];
        }
        __syncthreads();
    }
#pragma unroll
    for (int i = 0; i < 4; i++)
#pragma unroll
        for (int j = 0; j < 4; j++) {
            int m = m0 + ty * 4 + i, n = n0 + tx * 4 + j;
            float v = acc[i][j] + bias[n];
            g_hd_f32[0][m * HDIM + n] = v;
            g_hd_f16[0][m * HDIM + n] = __float2half(v);
        }
}

// ---------------------------------------------------------------------------
// setup kernels
// ---------------------------------------------------------------------------
__global__ void convert_weights_kernel(const float* __restrict__ Whh0,
                                       const float* __restrict__ Wih1,
                                       const float* __restrict__ Whh1,
                                       const float* __restrict__ cWhh) {
    int i = blockIdx.x * blockDim.x + threadIdx.x;
    if (i < G3H * HDIM) {
        g_Whh0[i] = __float2half(Whh0[i]);
        g_Wih1[i] = __float2half(Wih1[i]);
        g_Whh1[i] = __float2half(Whh1[i]);
        g_cWhh[i] = __float2half(cWhh[i]);
    }
}

__global__ void init_kernel(const float* __restrict__ src) {
    int i = blockIdx.x * blockDim.x + threadIdx.x;
    if (i < BATCH * HDIM) {
        g_h0_f32[1][i] = 0.f;
        g_h1_f32[1][i] = 0.f;
        g_h0_f16[1][i] = __float2half(0.f);
        g_h1_f16[1][i] = __float2half(0.f);
    }
    if (i < BATCH) g_lastv[i] = src[i * (TSTEPS * 8) + (TSTEPS - 1) * 8];
    if (i == 0) { g_bar_cnt = 0; g_bar_gen = 0; }
}

// ---------------------------------------------------------------------------
extern "C" void kernel_launch(void* const* d_in, const int* in_sizes, int n_in,
                              void* d_out, int out_size) {
    const float* src   = (const float*)d_in[0];
    const float* tf    = (const float*)d_in[1];
    const float* Wih0  = (const float*)d_in[2];
    const float* Whh0  = (const float*)d_in[3];
    const float* bih0  = (const float*)d_in[4];
    const float* bhh0  = (const float*)d_in[5];
    const float* Wih1  = (const float*)d_in[6];
    const float* Whh1  = (const float*)d_in[7];
    const float* bih1  = (const float*)d_in[8];
    const float* bhh1  = (const float*)d_in[9];
    const float* dec0W = (const float*)d_in[10];
    const float* dec0b = (const float*)d_in[11];
    const float* cWih  = (const float*)d_in[12];
    const float* cWhh  = (const float*)d_in[13];
    const float* cbih  = (const float*)d_in[14];
    const float* cbhh  = (const float*)d_in[15];
    const float* fcW   = (const float*)d_in[16];
    const float* fcb   = (const float*)d_in[17];
    float* out = (float*)d_out;

    cudaFuncSetAttribute(enc_persistent,
                         cudaFuncAttributeMaxDynamicSharedMemorySize, PSMEM);
    cudaFuncSetAttribute(dec_step_kernel,
                         cudaFuncAttributeMaxDynamicSharedMemorySize, DEC_SMEM);

    convert_weights_kernel<<<(G3H * HDIM + 255) / 256, 256>>>(Whh0, Wih1, Whh1, cWhh);
    init_kernel<<<(BATCH * HDIM + 255) / 256, 256>>>(src);

    // Whole encoder in ONE persistent launch
    enc_persistent<<<NBLK, 256, PSMEM>>>(src, bih0, bhh0, Wih0, bih1, bhh1);

    // Decoder init + 48 steps
    dec0_kernel<<<dim3(8, 8), 256>>>(dec0W, dec0b);
    for (int s = 0; s < HORIZON; s++) {
        dec_step_kernel<<<128, 256, DEC_SMEM>>>(s, tf, cbih, cbhh, cWih);
        fc_kernel<<<64, 256>>>(s, fcW, fcb, out);
    }
}

// round 13
// speedup vs baseline: 1.2751x; 1.2708x over previous
#include <cuda_runtime.h>
#include <cuda_fp16.h>
#include <cstdint>

// ---------------------------------------------------------------------------
// Seq2SeqForecast: 2-layer GRU encoder (B=512, T=336, H=512) + 48-step GRU
// decoder with scalar head.
//
// R12 = R9 (best passing, 6614us) + Programmatic Dependent Launch:
//  * every step kernel is launched with programmaticStreamSerialization; the
//    next kernel's blocks start early and prefetch their WEIGHT tiles
//    (independent of h) via cp.async BEFORE griddepcontrol.wait, overlapping
//    the previous grid's tail + launch latency.
//  * griddepcontrol.wait gates only the h-dependent A-tile staging.
// Persistent-kernel branch (R10/R11) abandoned: grid-barrier + 1-CTA/SM
// straggler cost exceeded the launch overhead it removed.
// ---------------------------------------------------------------------------

#define HDIM   512
#define BATCH  512
#define TSTEPS 336
#define HORIZON 48
#define G3H    (3 * HDIM)          // 1536

// fp16 weight copies
__device__ __half g_Whh0[G3H * HDIM];
__device__ __half g_Wih1[G3H * HDIM];
__device__ __half g_Whh1[G3H * HDIM];
__device__ __half g_cWhh[G3H * HDIM];

// hidden-state ping-pong buffers (fp32 master + fp16 shadow for MMA)
__device__ float  g_h0_f32[2][BATCH * HDIM];
__device__ __half g_h0_f16[2][BATCH * HDIM];
__device__ float  g_h1_f32[2][BATCH * HDIM];
__device__ __half g_h1_f16[2][BATCH * HDIM];
__device__ float  g_hd_f32[2][BATCH * HDIM];
__device__ __half g_hd_f16[2][BATCH * HDIM];
__device__ float  g_lastv[BATCH];

// ---------------------------------------------------------------------------
// helpers
// ---------------------------------------------------------------------------
__device__ __forceinline__ void mma16816(float (&c)[4], const uint32_t (&a)[4],
                                         uint32_t b0, uint32_t b1) {
    asm volatile(
        "mma.sync.aligned.m16n8k16.row.col.f32.f16.f16.f32 "
        "{%0,%1,%2,%3}, {%4,%5,%6,%7}, {%8,%9}, {%0,%1,%2,%3};\n"
        : "+f"(c[0]), "+f"(c[1]), "+f"(c[2]), "+f"(c[3])
        : "r"(a[0]), "r"(a[1]), "r"(a[2]), "r"(a[3]), "r"(b0), "r"(b1));
}

__device__ __forceinline__ void ldsm4(uint32_t (&r)[4], uint32_t saddr) {
    asm volatile(
        "ldmatrix.sync.aligned.m8n8.x4.shared.b16 {%0,%1,%2,%3}, [%4];\n"
        : "=r"(r[0]), "=r"(r[1]), "=r"(r[2]), "=r"(r[3]) : "r"(saddr));
}

__device__ __forceinline__ float sigmoidf_(float x) {
    return 1.0f / (1.0f + expf(-x));
}

__device__ __forceinline__ void cp16(uint32_t dst, const void* src) {
    asm volatile("cp.async.cg.shared.global [%0], [%1], 16;\n"
                 :: "r"(dst), "l"(src));
}
__device__ __forceinline__ void cp_commit() {
    asm volatile("cp.async.commit_group;\n");
}
template <int N>
__device__ __forceinline__ void cp_wait() {
    asm volatile("cp.async.wait_group %0;\n" :: "n"(N));
}

// PDL: no-ops when the launch lacks the programmatic-serialization attribute.
__device__ __forceinline__ void pdl_wait() {
    asm volatile("griddepcontrol.wait;" ::: "memory");
}
__device__ __forceinline__ void pdl_trigger() {
    asm volatile("griddepcontrol.launch_dependents;" ::: "memory");
}

// ---------------------------------------------------------------------------
// Core GRU tile: block computes a 64(batch) x 32(hidden) tile of h_new.
// gh = h_prev @ Wghᵀ (+bhh) always via MMA.
// gi either via MMA (HAS_GI: layer1) or inline small dot (IN_FEAT = 8 or 9).
// Double-buffered smem (stride BSTRIDE halves per buffer); per-buffer layout
// (row stride 72 halves): As0[64] Bs0[96] [As1[64] Bs1[96] if HAS_GI].
// PDLW: stage chunk-0 WEIGHTS before griddepcontrol.wait (independent of the
// producer kernel), A tiles after.
// ---------------------------------------------------------------------------
template <bool HAS_GI, int IN_FEAT, bool HAS_XFIRST, int BSTRIDE, bool PDLW>
__device__ __forceinline__ void gru_block(
    __half* __restrict__ smem, int m0, int n0,
    const __half* __restrict__ Agh, const __half* __restrict__ Wgh,
    const __half* __restrict__ Agi, const __half* __restrict__ Wgi,
    const float* __restrict__ bih, const float* __restrict__ bhh,
    const float* __restrict__ WihS,  // [1536 x IN_FEAT] small input weights
    const float* __restrict__ xrow, int xstride,
    const float* __restrict__ xfirst,
    const float* __restrict__ hprev, float* __restrict__ hout,
    __half* __restrict__ hout16) {

    const int tid  = threadIdx.x;
    const int lane = tid & 31;
    const int wid  = tid >> 5;       // 8 warps
    const int wm   = wid >> 1;       // 4 warps along M
    const int wn   = wid & 1;        // 2 warps along N
    const int g4   = lane >> 2;      // 0..7
    const int t4   = lane & 3;       // 0..3

    // ---- cp.async staging setup ----
    const int r8 = tid >> 3;         // 0..31
    const int c8 = tid & 7;          // 0..7 (uint4 within 64-half k-chunk)
    const uint32_t sbase = (uint32_t)__cvta_generic_to_shared(smem);
    const uint32_t sA  = sbase + (uint32_t)((r8 * 72 + c8 * 8) * 2);
    const uint32_t sB  = sbase + (uint32_t)((64 * 72 + r8 * 72 + c8 * 8) * 2);
    const __half* pA0   = Agh + (m0 + r8) * HDIM + c8 * 8;
    const __half* pB0_0 = Wgh + (0 * HDIM + n0 + r8) * HDIM + c8 * 8;
    const __half* pB0_1 = Wgh + (1 * HDIM + n0 + r8) * HDIM + c8 * 8;
    const __half* pB0_2 = Wgh + (2 * HDIM + n0 + r8) * HDIM + c8 * 8;
    const __half* pA1   = HAS_GI ? Agi + (m0 + r8) * HDIM + c8 * 8 : nullptr;
    const __half* pB1_0 = HAS_GI ? Wgi + (0 * HDIM + n0 + r8) * HDIM + c8 * 8 : nullptr;
    const __half* pB1_1 = HAS_GI ? Wgi + (1 * HDIM + n0 + r8) * HDIM + c8 * 8 : nullptr;
    const __half* pB1_2 = HAS_GI ? Wgi + (2 * HDIM + n0 + r8) * HDIM + c8 * 8 : nullptr;

    auto stageB = [&](int ks) {
        const uint32_t bo = (uint32_t)((ks & 1) * BSTRIDE * 2);
        const int ko = ks * 64;
        cp16(sB + bo, pB0_0 + ko);
        cp16(sB + bo + 32 * 72 * 2, pB0_1 + ko);
        cp16(sB + bo + 64 * 72 * 2, pB0_2 + ko);
        if (HAS_GI) {
            const uint32_t bo1 = bo + 160 * 72 * 2;
            cp16(sB + bo1, pB1_0 + ko);
            cp16(sB + bo1 + 32 * 72 * 2, pB1_1 + ko);
            cp16(sB + bo1 + 64 * 72 * 2, pB1_2 + ko);
        }
    };
    auto stageA = [&](int ks) {
        const uint32_t bo = (uint32_t)((ks & 1) * BSTRIDE * 2);
        const int ko = ks * 64;
        cp16(sA + bo, pA0 + ko);
        cp16(sA + bo + 32 * 72 * 2, pA0 + 32 * HDIM + ko);
        if (HAS_GI) {
            const uint32_t bo1 = bo + 160 * 72 * 2;
            cp16(sA + bo1, pA1 + ko);
            cp16(sA + bo1 + 32 * 72 * 2, pA1 + 32 * HDIM + ko);
        }
    };

    float acc_gh[3][2][4];
    float acc_gi[3][2][4];
#pragma unroll
    for (int g = 0; g < 3; g++)
#pragma unroll
        for (int nh = 0; nh < 2; nh++)
#pragma unroll
            for (int i = 0; i < 4; i++) {
                acc_gh[g][nh][i] = 0.f;
                if (HAS_GI) acc_gi[g][nh][i] = 0.f;
            }

    // ldmatrix per-lane addressing (x4 fragment order matches mma A/B).
    const int lane15 = lane & 15;
    const int lhi8   = (lane >> 4) * 8;
    const uint32_t aoff = (uint32_t)(((wm * 16 + lane15) * 72 + lhi8) * 2);
    uint32_t boff[3];
#pragma unroll
    for (int g = 0; g < 3; g++)
        boff[g] = (uint32_t)(((64 + g * 32 + wn * 16 + lane15) * 72 + lhi8) * 2);
    const uint32_t GIOFF = (uint32_t)(160 * 72 * 2);

    // chunk 0: weights before the PDL dependency gate, A tiles after.
    stageB(0); cp_commit();
    if (PDLW) pdl_wait();
    stageA(0); cp_commit();

    for (int ks = 0; ks < 8; ks++) {
        if (ks < 7) { stageA(ks + 1); stageB(ks + 1); cp_commit(); cp_wait<1>(); }
        else        { cp_wait<0>(); }
        __syncthreads();

        const uint32_t base = sbase + (uint32_t)((ks & 1) * BSTRIDE * 2);

#pragma unroll
        for (int kk = 0; kk < 64; kk += 16) {
            uint32_t a0[4], a1[4];
            ldsm4(a0, base + aoff + kk * 2);
            if (HAS_GI) ldsm4(a1, base + GIOFF + aoff + kk * 2);
#pragma unroll
            for (int g = 0; g < 3; g++) {
                uint32_t b[4];
                ldsm4(b, base + boff[g] + kk * 2);
                mma16816(acc_gh[g][0], a0, b[0], b[2]);
                mma16816(acc_gh[g][1], a0, b[1], b[3]);
                if (HAS_GI) {
                    uint32_t c[4];
                    ldsm4(c, base + GIOFF + boff[g] + kk * 2);
                    mma16816(acc_gi[g][0], a1, c[0], c[2]);
                    mma16816(acc_gi[g][1], a1, c[1], c[3]);
                }
            }
        }
        __syncthreads();
    }

    // ---- epilogue: gates fully in registers (known mma C layout) ----
    const int mbase = m0 + wm * 16 + g4;
    const int nbase = n0 + wn * 16 + t4 * 2;

#pragma unroll
    for (int hm = 0; hm < 2; hm++) {
        const int row = mbase + hm * 8;
        float xv[IN_FEAT > 0 ? IN_FEAT : 1];
        if constexpr (!HAS_GI) {
            if constexpr (HAS_XFIRST) {
                xv[0] = xfirst[row];
#pragma unroll
                for (int i = 1; i < IN_FEAT; i++)
                    xv[i] = xrow[row * xstride + i - 1];
            } else {
#pragma unroll
                for (int i = 0; i < IN_FEAT; i++)
                    xv[i] = xrow[row * xstride + i];
            }
        }
#pragma unroll
        for (int nh = 0; nh < 2; nh++) {
            const int j0 = nbase + nh * 8;
            float2 hp = *(const float2*)(hprev + row * HDIM + j0);
            float2 ho;
#pragma unroll
            for (int cc = 0; cc < 2; cc++) {
                const int j = j0 + cc;
                const int ci = hm * 2 + cc;
                float gir, giz, gin;
                if constexpr (HAS_GI) {
                    gir = acc_gi[0][nh][ci] + bih[j];
                    giz = acc_gi[1][nh][ci] + bih[HDIM + j];
                    gin = acc_gi[2][nh][ci] + bih[2 * HDIM + j];
                } else {
                    gir = bih[j];
                    giz = bih[HDIM + j];
                    gin = bih[2 * HDIM + j];
                    const float* wr = WihS + j * IN_FEAT;
                    const float* wz = WihS + (HDIM + j) * IN_FEAT;
                    const float* wn_ = WihS + (2 * HDIM + j) * IN_FEAT;
#pragma unroll
                    for (int i = 0; i < IN_FEAT; i++) {
                        gir += xv[i] * wr[i];
                        giz += xv[i] * wz[i];
                        gin += xv[i] * wn_[i];
                    }
                }
                float ghr = acc_gh[0][nh][ci] + bhh[j];
                float ghz = acc_gh[1][nh][ci] + bhh[HDIM + j];
                float ghn = acc_gh[2][nh][ci] + bhh[2 * HDIM + j];
                float rg = sigmoidf_(gir + ghr);
                float zg = sigmoidf_(giz + ghz);
                float ng = tanhf(gin + rg * ghn);
                float hpv = cc ? hp.y : hp.x;
                float hv = (1.0f - zg) * ng + zg * hpv;
                if (cc) ho.y = hv; else ho.x = hv;
            }
            *(float2*)(hout + row * HDIM + j0) = ho;
            __half2 h2;
            h2.x = __float2half(ho.x);
            h2.y = __float2half(ho.y);
            *(__half2*)(hout16 + row * HDIM + j0) = h2;
        }
    }
}

#define ENC_BSTRIDE (320 * 72)
#define DEC_BSTRIDE (160 * 72)
#define ENC_SMEM    (2 * ENC_BSTRIDE * 2)   // 92160 bytes
#define DEC_SMEM    (2 * DEC_BSTRIDE * 2)   // 46080 bytes

// ---------------------------------------------------------------------------
// Fused encoder step: blocks [0,128) -> layer0 h0[t]; [128,256) -> layer1
// h1[t-1] (one-step lag makes the two halves independent).
// ---------------------------------------------------------------------------
__global__ __launch_bounds__(256, 2)
void enc_step_kernel(int t, const float* __restrict__ src,
                     const float* __restrict__ bih0, const float* __restrict__ bhh0,
                     const float* __restrict__ Wih0,
                     const float* __restrict__ bih1, const float* __restrict__ bhh1) {
    extern __shared__ __align__(16) __half dynsmem[];
    const int role = (blockIdx.x < 128) ? 0 : 1;
    const int bid = blockIdx.x & 127;
    const int m0 = (bid >> 4) * 64;
    const int n0 = (bid & 15) * 32;

    if (role == 0) {
        if (t < TSTEPS) {
            const int pw = t & 1, pr = (t + 1) & 1;   // h0[t-1] at parity (t-1)&1
            gru_block<false, 8, false, ENC_BSTRIDE, true>(dynsmem, m0, n0,
                g_h0_f16[pr], g_Whh0, nullptr, nullptr,
                bih0, bhh0, Wih0, src + t * 8, TSTEPS * 8, nullptr,
                g_h0_f32[pr], g_h0_f32[pw], g_h0_f16[pw]);
        }
    } else {
        if (t >= 1) {
            const int tt = t - 1;                     // computing h1[tt]
            const int pw = tt & 1, pr = (tt + 1) & 1; // h1[tt-1] parity
            gru_block<true, 0, false, ENC_BSTRIDE, true>(dynsmem, m0, n0,
                g_h1_f16[pr], g_Whh1, g_h0_f16[tt & 1], g_Wih1,
                bih1, bhh1, nullptr, nullptr, 0, nullptr,
                g_h1_f32[pr], g_h1_f32[pw], g_h1_f16[pw]);
        }
    }
    pdl_trigger();
}

// ---------------------------------------------------------------------------
// Decoder GRU cell step (gi inline from [last_value, tf_t], 9 features)
// ---------------------------------------------------------------------------
__global__ __launch_bounds__(256, 2)
void dec_step_kernel(int s, const float* __restrict__ tf,
                     const float* __restrict__ cbih, const float* __restrict__ cbhh,
                     const float* __restrict__ cWih) {
    extern __shared__ __align__(16) __half dynsmem2[];
    const int bid = blockIdx.x;
    const int m0 = (bid >> 4) * 64;
    const int n0 = (bid & 15) * 32;
    const int pr = s & 1, pw = (s + 1) & 1;
    gru_block<false, 9, true, DEC_BSTRIDE, true>(dynsmem2, m0, n0,
        g_hd_f16[pr], g_cWhh, nullptr, nullptr,
        cbih, cbhh, cWih, tf + s * 8, HORIZON * 8, g_lastv,
        g_hd_f32[pr], g_hd_f32[pw], g_hd_f16[pw]);
    pdl_trigger();
}

// ---------------------------------------------------------------------------
// fc head: pred[b] = hidden[b] . fc_W + fc_b ; also feeds next last_value
// ---------------------------------------------------------------------------
__global__ __launch_bounds__(256)
void fc_kernel(int s, const float* __restrict__ fcW, const float* __restrict__ fcb,
               float* __restrict__ out) {
    pdl_wait();
    const int b = blockIdx.x * 8 + (threadIdx.x >> 5);
    const int lane = threadIdx.x & 31;
    const float* h = g_hd_f32[(s + 1) & 1] + b * HDIM;
    float sum = 0.f;
#pragma unroll
    for (int k = lane; k < HDIM; k += 32) sum += h[k] * fcW[k];
#pragma unroll
    for (int o = 16; o; o >>= 1) sum += __shfl_xor_sync(0xffffffffu, sum, o);
    if (lane == 0) {
        float p = sum + fcb[0];
        out[b * HORIZON + s] = p;
        g_lastv[b] = p;
    }
    pdl_trigger();
}

// ---------------------------------------------------------------------------
// dec0 linear: hidden0 = h1[T-1] @ dec0_Wᵀ + dec0_b  (one-time, fp32 SIMT)
// ---------------------------------------------------------------------------
__global__ __launch_bounds__(256)
void dec0_kernel(const float* __restrict__ W, const float* __restrict__ bias) {
    pdl_wait();
    __shared__ float As[64][17];
    __shared__ float Ws[64][17];
    const float* A = g_h1_f32[(TSTEPS - 1) & 1];
    const int m0 = blockIdx.y * 64, n0 = blockIdx.x * 64;
    const int tx = threadIdx.x & 15, ty = threadIdx.x >> 4;
    float acc[4][4] = {};
    for (int k0 = 0; k0 < HDIM; k0 += 16) {
#pragma unroll
        for (int i = 0; i < 4; i++) {
            int idx = threadIdx.x + i * 256;
            int r = idx >> 4, c = idx & 15;
            As[r][c] = A[(m0 + r) * HDIM + k0 + c];
            Ws[r][c] = W[(n0 + r) * HDIM + k0 + c];
        }
        __syncthreads();
#pragma unroll
        for (int kk = 0; kk < 16; kk++) {
            float a[4], w[4];
#pragma unroll
            for (int i = 0; i < 4; i++) { a[i] = As[ty * 4 + i][kk]; w[i] = Ws[tx * 4 + i][kk]; }
#pragma unroll
            for (int i = 0; i < 4; i++)
#pragma unroll
                for (int j = 0; j < 4; j++) acc[i][j] += a[i] * w[j];
        }
        __syncthreads();
    }
#pragma unroll
    for (int i = 0; i < 4; i++)
#pragma unroll
        for (int j = 0; j < 4; j++) {
            int m = m0 + ty * 4 + i, n = n0 + tx * 4 + j;
            float v = acc[i][j] + bias[n];
            g_hd_f32[0][m * HDIM + n] = v;
            g_hd_f16[0][m * HDIM + n] = __float2half(v);
        }
    pdl_trigger();
}

// ---------------------------------------------------------------------------
// setup kernels
// ---------------------------------------------------------------------------
__global__ void convert_weights_kernel(const float* __restrict__ Whh0,
                                       const float* __restrict__ Wih1,
                                       const float* __restrict__ Whh1,
                                       const float* __restrict__ cWhh) {
    int i = blockIdx.x * blockDim.x + threadIdx.x;
    if (i < G3H * HDIM) {
        g_Whh0[i] = __float2half(Whh0[i]);
        g_Wih1[i] = __float2half(Wih1[i]);
        g_Whh1[i] = __float2half(Whh1[i]);
        g_cWhh[i] = __float2half(cWhh[i]);
    }
}

__global__ void init_kernel(const float* __restrict__ src) {
    int i = blockIdx.x * blockDim.x + threadIdx.x;
    if (i < BATCH * HDIM) {
        g_h0_f32[1][i] = 0.f;
        g_h1_f32[1][i] = 0.f;
        g_h0_f16[1][i] = __float2half(0.f);
        g_h1_f16[1][i] = __float2half(0.f);
    }
    if (i < BATCH) g_lastv[i] = src[i * (TSTEPS * 8) + (TSTEPS - 1) * 8];
}

// ---------------------------------------------------------------------------
// PDL launch helper
// ---------------------------------------------------------------------------
static void launch_pdl(const void* func, dim3 grid, dim3 block, size_t smem,
                       void** args) {
    cudaLaunchConfig_t cfg = {};
    cfg.gridDim = grid;
    cfg.blockDim = block;
    cfg.dynamicSmemBytes = smem;
    cfg.stream = 0;
    cudaLaunchAttribute at[1];
    at[0].id = cudaLaunchAttributeProgrammaticStreamSerialization;
    at[0].val.programmaticStreamSerializationAllowed = 1;
    cfg.attrs = at;
    cfg.numAttrs = 1;
    cudaLaunchKernelExC(&cfg, func, args);
}

// ---------------------------------------------------------------------------
extern "C" void kernel_launch(void* const* d_in, const int* in_sizes, int n_in,
                              void* d_out, int out_size) {
    const float* src   = (const float*)d_in[0];
    const float* tf    = (const float*)d_in[1];
    const float* Wih0  = (const float*)d_in[2];
    const float* Whh0  = (const float*)d_in[3];
    const float* bih0  = (const float*)d_in[4];
    const float* bhh0  = (const float*)d_in[5];
    const float* Wih1  = (const float*)d_in[6];
    const float* Whh1  = (const float*)d_in[7];
    const float* bih1  = (const float*)d_in[8];
    const float* bhh1  = (const float*)d_in[9];
    const float* dec0W = (const float*)d_in[10];
    const float* dec0b = (const float*)d_in[11];
    const float* cWih  = (const float*)d_in[12];
    const float* cWhh  = (const float*)d_in[13];
    const float* cbih  = (const float*)d_in[14];
    const float* cbhh  = (const float*)d_in[15];
    const float* fcW   = (const float*)d_in[16];
    const float* fcb   = (const float*)d_in[17];
    float* out = (float*)d_out;

    cudaFuncSetAttribute(enc_step_kernel,
                         cudaFuncAttributeMaxDynamicSharedMemorySize, ENC_SMEM);
    cudaFuncSetAttribute(dec_step_kernel,
                         cudaFuncAttributeMaxDynamicSharedMemorySize, DEC_SMEM);

    convert_weights_kernel<<<(G3H * HDIM + 255) / 256, 256>>>(Whh0, Wih1, Whh1, cWhh);
    init_kernel<<<(BATCH * HDIM + 255) / 256, 256>>>(src);

    // Encoder: T+1 fused launches with PDL chaining
    for (int t = 0; t <= TSTEPS; t++) {
        int tv = t;
        void* args[] = { &tv, (void*)&src, (void*)&bih0, (void*)&bhh0,
                         (void*)&Wih0, (void*)&bih1, (void*)&bhh1 };
        launch_pdl((const void*)enc_step_kernel, dim3(256), dim3(256),
                   ENC_SMEM, args);
    }

    // Decoder init + 48 steps, all PDL-chained
    {
        void* args[] = { (void*)&dec0W, (void*)&dec0b };
        launch_pdl((const void*)dec0_kernel, dim3(8, 8), dim3(256), 0, args);
    }
    for (int s = 0; s < HORIZON; s++) {
        int sv = s;
        {
            void* args[] = { &sv, (void*)&tf, (void*)&cbih, (void*)&cbhh,
                             (void*)&cWih };
            launch_pdl((const void*)dec_step_kernel, dim3(128), dim3(256),
                       DEC_SMEM, args);
        }
        {
            void* args[] = { &sv, (void*)&fcW, (void*)&fcb, (void*)&out };
            launch_pdl((const void*)fc_kernel, dim3(64), dim3(256), 0, args);
        }
    }
}